// round 1
// baseline (speedup 1.0000x reference)
#include <cuda_runtime.h>
#include <math.h>
#include <stdint.h>

#define B_ 64
#define T_ 1024
#define H_ 256
#define M_ (B_*T_)   /* 65536 rows for the projection GEMMs */

// Scratch (device globals — no runtime allocation allowed)
__device__ float g_xp[B_*T_*H_];   // input-projection result for current layer
__device__ float g_h [B_*T_*H_];   // layer-0 hidden sequence

// ---------------------------------------------------------------------------
// packed f32x2 helpers (sm_100+): one instr = 2 fp32 FMAs
// ---------------------------------------------------------------------------
__device__ __forceinline__ unsigned long long ffma2(unsigned long long a,
                                                    unsigned long long b,
                                                    unsigned long long c) {
    unsigned long long d;
    asm("fma.rn.f32x2 %0, %1, %2, %3;" : "=l"(d) : "l"(a), "l"(b), "l"(c));
    return d;
}
__device__ __forceinline__ unsigned long long pack2(float lo, float hi) {
    unsigned long long r;
    asm("mov.b64 %0, {%1, %2};"
        : "=l"(r) : "r"(__float_as_uint(lo)), "r"(__float_as_uint(hi)));
    return r;
}
__device__ __forceinline__ float2 unpack2(unsigned long long v) {
    uint32_t lo, hi;
    asm("mov.b64 {%0, %1}, %2;" : "=r"(lo), "=r"(hi) : "l"(v));
    return make_float2(__uint_as_float(lo), __uint_as_float(hi));
}
__device__ __forceinline__ uint32_t smem_u32(const void* p) {
    return (uint32_t)__cvta_generic_to_shared(p);
}

// ---------------------------------------------------------------------------
// Projection GEMM: out[M,256] = A[M,256] @ W[256,256]^T + bias
// BM=128, BN=64, BK=16, 256 threads, per-thread 8(M)x4(N) with f32x2 pairs
// along M (a-pairs load packed straight from SMEM; only b needs duplication).
// ---------------------------------------------------------------------------
__global__ void __launch_bounds__(256, 2)
gemm_bias(const float* __restrict__ A, const float* __restrict__ W,
          const float* __restrict__ bias, float* __restrict__ out)
{
    __shared__ __align__(16) float As[16][128];
    __shared__ __align__(16) float Bs[16][64];

    const int tid = threadIdx.x;
    const int m0  = blockIdx.x * 128;
    const int n0  = blockIdx.y * 64;
    const int tx  = tid & 15;        // N direction (4 cols)
    const int ty  = tid >> 4;        // M direction (8 rows)
    const int lm  = tid >> 1;        // A-load: row within tile
    const int ak  = (tid & 1) * 8;   // A-load: k offset (8 floats)
    const int ln  = tid & 63;        // W-load: row within tile
    const int bk  = (tid >> 6) * 4;  // W-load: k offset (4 floats)

    unsigned long long acc[4][4];
#pragma unroll
    for (int p = 0; p < 4; p++)
#pragma unroll
        for (int n = 0; n < 4; n++) acc[p][n] = 0ull;

    const float* Arow = A + (size_t)(m0 + lm) * H_;
    const float* Wrow = W + (size_t)(n0 + ln) * H_;

    for (int k0 = 0; k0 < H_; k0 += 16) {
        float4 av0 = *(const float4*)(Arow + k0 + ak);
        float4 av1 = *(const float4*)(Arow + k0 + ak + 4);
        float4 bv0 = *(const float4*)(Wrow + k0 + bk);
        As[ak+0][lm] = av0.x; As[ak+1][lm] = av0.y;
        As[ak+2][lm] = av0.z; As[ak+3][lm] = av0.w;
        As[ak+4][lm] = av1.x; As[ak+5][lm] = av1.y;
        As[ak+6][lm] = av1.z; As[ak+7][lm] = av1.w;
        Bs[bk+0][ln] = bv0.x; Bs[bk+1][ln] = bv0.y;
        Bs[bk+2][ln] = bv0.z; Bs[bk+3][ln] = bv0.w;
        __syncthreads();
#pragma unroll
        for (int k = 0; k < 16; k++) {
            const ulonglong2* ap = (const ulonglong2*)&As[k][ty * 8];
            ulonglong2 q0 = ap[0];   // rows (0,1),(2,3)
            ulonglong2 q1 = ap[1];   // rows (4,5),(6,7)
            float4 bv = *(const float4*)&Bs[k][tx * 4];
            unsigned long long b0 = pack2(bv.x, bv.x);
            unsigned long long b1 = pack2(bv.y, bv.y);
            unsigned long long b2 = pack2(bv.z, bv.z);
            unsigned long long b3 = pack2(bv.w, bv.w);
            acc[0][0]=ffma2(q0.x,b0,acc[0][0]); acc[0][1]=ffma2(q0.x,b1,acc[0][1]);
            acc[0][2]=ffma2(q0.x,b2,acc[0][2]); acc[0][3]=ffma2(q0.x,b3,acc[0][3]);
            acc[1][0]=ffma2(q0.y,b0,acc[1][0]); acc[1][1]=ffma2(q0.y,b1,acc[1][1]);
            acc[1][2]=ffma2(q0.y,b2,acc[1][2]); acc[1][3]=ffma2(q0.y,b3,acc[1][3]);
            acc[2][0]=ffma2(q1.x,b0,acc[2][0]); acc[2][1]=ffma2(q1.x,b1,acc[2][1]);
            acc[2][2]=ffma2(q1.x,b2,acc[2][2]); acc[2][3]=ffma2(q1.x,b3,acc[2][3]);
            acc[3][0]=ffma2(q1.y,b0,acc[3][0]); acc[3][1]=ffma2(q1.y,b1,acc[3][1]);
            acc[3][2]=ffma2(q1.y,b2,acc[3][2]); acc[3][3]=ffma2(q1.y,b3,acc[3][3]);
        }
        __syncthreads();
    }

    float4 bb = *(const float4*)(bias + n0 + tx * 4);
#pragma unroll
    for (int p = 0; p < 4; p++) {
        float2 c0 = unpack2(acc[p][0]);
        float2 c1 = unpack2(acc[p][1]);
        float2 c2 = unpack2(acc[p][2]);
        float2 c3 = unpack2(acc[p][3]);
        float4 lo = make_float4(c0.x + bb.x, c1.x + bb.y, c2.x + bb.z, c3.x + bb.w);
        float4 hi = make_float4(c0.y + bb.x, c1.y + bb.y, c2.y + bb.z, c3.y + bb.w);
        size_t r = (size_t)(m0 + ty * 8 + 2 * p) * H_ + n0 + tx * 4;
        *(float4*)(out + r)      = lo;
        *(float4*)(out + r + H_) = hi;
    }
}

// ---------------------------------------------------------------------------
// Recurrent scan: one 2-CTA cluster per batch element.
//   - Each CTA holds half of W_hh in REGISTERS (128 fp32 per thread).
//   - h (256 floats) lives in double-buffered SMEM; halves exchanged per step
//     via st.shared::cluster, synced with split barrier.cluster arrive/wait.
//   - Thread t: output j = rank*128 + (t&127), k-half = t>>7; 2-way partial
//     reduction through SMEM. FMAs as packed f32x2 (h broadcast-LDS, free).
// ---------------------------------------------------------------------------
__global__ void __launch_bounds__(256, 1) __cluster_dims__(2, 1, 1)
elman_scan(const float* __restrict__ xp, const float* __restrict__ Whh,
           float* __restrict__ ys)
{
    __shared__ __align__(16) float hbuf[2][H_];
    __shared__ float part[128];

    const int tid   = threadIdx.x;
    const int jl    = tid & 127;
    const int khalf = tid >> 7;
    const int rank  = (int)(blockIdx.x & 1);   // cluster ctarank (contiguous x)
    const int batch = (int)(blockIdx.x >> 1);
    const int jg    = rank * 128 + jl;

    // Persistent weights: W_hh[jg][khalf*128 .. +127] as 64 packed f32x2
    unsigned long long w[64];
    {
        const ulonglong2* wv =
            (const ulonglong2*)(Whh + (size_t)jg * H_ + khalf * 128);
#pragma unroll
        for (int i = 0; i < 32; i++) {
            ulonglong2 v = wv[i];
            w[2*i] = v.x; w[2*i+1] = v.y;
        }
    }

    for (int i = tid; i < 2 * H_; i += 256) (&hbuf[0][0])[i] = 0.0f;
    __syncthreads();

    const float* xpb = xp + (size_t)batch * T_ * H_;
    float*       ysb = ys + (size_t)batch * T_ * H_;
    const uint32_t my_h = smem_u32(&hbuf[0][0]);

    float x_cur = 0.0f, x_next = 0.0f;
    if (khalf == 0) x_cur = xpb[jg];   // xp[t=0]

    asm volatile("barrier.cluster.arrive.aligned;" ::: "memory");

    for (int t = 0; t < T_; t++) {
        // Prefetch next timestep's xp while the cluster barrier settles
        if (khalf == 0 && t + 1 < T_)
            x_next = __ldg(xpb + (size_t)(t + 1) * H_ + jg);

        asm volatile("barrier.cluster.wait.aligned;" ::: "memory");

        const ulonglong2* hv =
            (const ulonglong2*)(hbuf[t & 1] + khalf * 128);
        unsigned long long a0 = 0ull, a1 = 0ull, a2 = 0ull, a3 = 0ull;
#pragma unroll
        for (int i = 0; i < 16; i++) {
            ulonglong2 p = hv[2*i];
            ulonglong2 q = hv[2*i + 1];
            a0 = ffma2(w[4*i+0], p.x, a0);
            a1 = ffma2(w[4*i+1], p.y, a1);
            a2 = ffma2(w[4*i+2], q.x, a2);
            a3 = ffma2(w[4*i+3], q.y, a3);
        }
        float2 f0 = unpack2(a0), f1 = unpack2(a1);
        float2 f2 = unpack2(a2), f3 = unpack2(a3);
        float s = ((f0.x + f0.y) + (f1.x + f1.y)) +
                  ((f2.x + f2.y) + (f3.x + f3.y));

        if (khalf) part[jl] = s;
        __syncthreads();

        if (!khalf) {
            float v = tanhf(s + part[jl] + x_cur);
            ysb[(size_t)t * H_ + jg] = v;
            if (t + 1 < T_) {
                int wb = (t + 1) & 1;
                hbuf[wb][jg] = v;                         // local copy
                uint32_t laddr = my_h + (uint32_t)(wb * H_ + jg) * 4u;
                uint32_t raddr;
                asm("mapa.shared::cluster.u32 %0, %1, %2;"
                    : "=r"(raddr) : "r"(laddr), "r"(rank ^ 1));
                asm volatile("st.shared::cluster.f32 [%0], %1;"
                             :: "r"(raddr), "f"(v) : "memory");
            }
        }
        x_cur = x_next;
        if (t + 1 < T_)
            asm volatile("barrier.cluster.arrive.aligned;" ::: "memory");
    }
    // Last iteration does no DSMEM writes and skipped its arrive: every
    // arrive is paired with a wait, and no peer write can land after exit.
}

// ---------------------------------------------------------------------------
// Launch: gemm0 -> scan0 -> gemm1 -> scan1 (all on the capture stream)
// ---------------------------------------------------------------------------
extern "C" void kernel_launch(void* const* d_in, const int* in_sizes, int n_in,
                              void* d_out, int out_size)
{
    const float* x     = (const float*)d_in[0];
    const float* W_ih0 = (const float*)d_in[1];
    const float* b_ih0 = (const float*)d_in[2];
    const float* W_hh0 = (const float*)d_in[3];
    const float* W_ih1 = (const float*)d_in[4];
    const float* b_ih1 = (const float*)d_in[5];
    const float* W_hh1 = (const float*)d_in[6];
    float* out = (float*)d_out;

    float *xp, *h;
    cudaGetSymbolAddress((void**)&xp, g_xp);
    cudaGetSymbolAddress((void**)&h,  g_h);

    dim3 ggrid(M_ / 128, H_ / 64);   // (512, 4)

    gemm_bias<<<ggrid, 256>>>(x, W_ih0, b_ih0, xp);
    elman_scan<<<B_ * 2, 256>>>(xp, W_hh0, h);
    gemm_bias<<<ggrid, 256>>>(h, W_ih1, b_ih1, xp);
    elman_scan<<<B_ * 2, 256>>>(xp, W_hh1, out);
}